// round 13
// baseline (speedup 1.0000x reference)
#include <cuda_runtime.h>
#include <cstdint>

// ---------------- problem constants ----------------
#define KNMS 100
#define BMAX 32
#define IOU_THR 0.3f

#define CS13 169
#define CS26 676
#define CS52 2704
#define N52V 676            // CS52/4 float4 per 52-scale anchor plane
#define BASE13 0
#define BASE26 507
#define BASE52 2535
#define LCAP 256
#define DBLK 13             // decode blocks per image
#define NBIN 4096           // 12-bit monotone-key histogram

// ---------------- device scratch ----------------
__device__ unsigned g_hist4[(size_t)BMAX * 4 * NBIN];   // per-CTA histogram slices
__device__ unsigned g_selctr[BMAX];                     // monotone arrival counters
__device__ unsigned g_decctr[BMAX];
__device__ unsigned long long g_selkey[BMAX * KNMS];    // sorted top-100 keys
__device__ float g_dec[BMAX * KNMS * 6];                // decoded boxes, rank order

__device__ __forceinline__ float sigmoidf_(float x) {
    return 1.0f / (1.0f + expf(-x));
}
__device__ __forceinline__ unsigned fkey_(float x) {    // monotone float->uint
    unsigned b = __float_as_uint(x);
    return (b & 0x80000000u) ? ~b : (b | 0x80000000u);
}

// ============================================================
// K1: top-100 select, 4 CTAs per image (grid = B*4, 1024 thr).
// Each CTA histograms 1/4 of the conf values (shared) and dumps
// its slice to global. Last-arriving CTA sums slices, picks the
// threshold bin, compacts candidates from the (L2-hot) inputs,
// and computes the exact stable rank -> g_selkey.
// ============================================================
__global__ void __launch_bounds__(1024)
select_kernel(const float* __restrict__ o13, const float* __restrict__ o26,
              const float* __restrict__ o52, const float* __restrict__ thr_p, int B)
{
    const int blk = blockIdx.x;
    const int b = blk >> 2;
    const int c = blk & 3;
    const int tid = threadIdx.x;
    const int lane = tid & 31;

    __shared__ unsigned hist[NBIN];               // 16 KB
    __shared__ unsigned psum[1024];
    __shared__ unsigned csum[128];
    __shared__ unsigned long long ckey[LCAP];
    __shared__ unsigned srank[LCAP];
    __shared__ unsigned long long selkey[KNMS];
    __shared__ int sh_cb, sh_kres, sh_P, sh_cnt, sh_islast;

    const float thr = *thr_p;
    const float lthr = logf(thr / (1.0f - thr)); // conf > thr  <=>  logit > lthr

    const float* b13 = o13 + (size_t)b * 255 * CS13;
    const float* b26 = o26 + (size_t)b * 255 * CS26;
    const float* b52 = o52 + (size_t)b * 255 * CS52;

    ((uint4*)hist)[tid] = make_uint4(0u, 0u, 0u, 0u);
    if (tid == 0) sh_cnt = 0;
    __syncthreads();

    // ---- Phase A (quarter): 52-scale vec quarter + one small scale ----
    if (tid < 3 * 169) {                          // 3 anchors x 169 float4
        int a = tid / 169, vv = tid - a * 169;
        int v = c * 169 + vv;
        float4 q = ((const float4*)(b52 + (size_t)a * 85 * CS52))[v];
        if (q.x > lthr) atomicAdd(&hist[fkey_(q.x) >> 20], 1u);
        if (q.y > lthr) atomicAdd(&hist[fkey_(q.y) >> 20], 1u);
        if (q.z > lthr) atomicAdd(&hist[fkey_(q.z) >> 20], 1u);
        if (q.w > lthr) atomicAdd(&hist[fkey_(q.w) >> 20], 1u);
    }
    if (c == 0) {
        if (tid < 3 * CS13) {                     // whole 13-scale
            int a = tid / CS13, cell = tid - a * CS13;
            float v = b13[(size_t)a * 85 * CS13 + cell];
            if (v > lthr) atomicAdd(&hist[fkey_(v) >> 20], 1u);
        }
    } else {
        if (tid < CS26) {                         // anchor (c-1) of 26-scale
            float v = b26[(size_t)(c - 1) * 85 * CS26 + tid];
            if (v > lthr) atomicAdd(&hist[fkey_(v) >> 20], 1u);
        }
    }
    __syncthreads();

    // ---- dump slice, signal arrival ----
    ((uint4*)(g_hist4 + (size_t)blk * NBIN))[tid] = ((uint4*)hist)[tid];
    __threadfence();
    __syncthreads();
    if (tid == 0) {
        unsigned old = atomicAdd(&g_selctr[b], 1u);
        sh_islast = ((old & 3u) == 3u) ? 1 : 0;   // monotone counter: replay-safe
    }
    __syncthreads();
    if (!sh_islast) return;

    // ---- last CTA: sum the 4 slices ----
    {
        const uint4* h0 = (const uint4*)(g_hist4 + (size_t)(b * 4 + 0) * NBIN);
        const uint4* h1 = (const uint4*)(g_hist4 + (size_t)(b * 4 + 1) * NBIN);
        const uint4* h2 = (const uint4*)(g_hist4 + (size_t)(b * 4 + 2) * NBIN);
        const uint4* h3 = (const uint4*)(g_hist4 + (size_t)(b * 4 + 3) * NBIN);
        uint4 q0 = h0[tid], q1 = h1[tid], q2 = h2[tid], q3 = h3[tid];
        uint4 s;
        s.x = q0.x + q1.x + q2.x + q3.x;
        s.y = q0.y + q1.y + q2.y + q3.y;
        s.z = q0.z + q1.z + q2.z + q3.z;
        s.w = q0.w + q1.w + q2.w + q3.w;
        ((uint4*)hist)[tid] = s;
        psum[tid] = s.x + s.y + s.z + s.w;
    }
    __syncthreads();
    if (tid < 128) {
        uint4 a0 = ((uint4*)psum)[tid * 2];
        uint4 a1 = ((uint4*)psum)[tid * 2 + 1];
        csum[tid] = a0.x + a0.y + a0.z + a0.w + a1.x + a1.y + a1.z + a1.w;
    }
    __syncthreads();

    // ---- warp 0: coarse + fine threshold pick ----
    if (tid < 32) {
        unsigned cc[4];
        int T = 0;
        #pragma unroll
        for (int r = 0; r < 4; ++r) { cc[r] = csum[lane * 4 + r]; T += (int)cc[r]; }
        int S = T;
        #pragma unroll
        for (int off = 1; off < 32; off <<= 1) {
            int v = __shfl_down_sync(0xffffffffu, S, off);
            if (lane + off < 32) S += v;
        }
        int Snext = __shfl_down_sync(0xffffffffu, S, 1);
        if (lane == 31) Snext = 0;
        if (S >= KNMS && Snext < KNMS) {
            int rem = Snext;
            #pragma unroll
            for (int r = 3; r >= 0; --r) {
                if (rem + (int)cc[r] >= KNMS) {
                    sh_cb = lane * 4 + r;
                    sh_kres = KNMS - rem;
                    break;
                }
                rem += (int)cc[r];
            }
        }
        __syncwarp();
        int cb = sh_cb, kres = sh_kres;
        unsigned h = hist[cb * 32 + lane];
        int S2 = (int)h;
        #pragma unroll
        for (int off = 1; off < 32; off <<= 1) {
            int v = __shfl_down_sync(0xffffffffu, S2, off);
            if (lane + off < 32) S2 += v;
        }
        int S2n = __shfl_down_sync(0xffffffffu, S2, 1);
        if (lane == 31) S2n = 0;
        if (S2 >= kres && S2n < kres) sh_P = cb * 32 + lane;
    }
    if (tid < LCAP) { ckey[tid] = 0ull; srank[tid] = 0u; }
    if (tid < KNMS) selkey[tid] = 0ull;
    __syncthreads();
    const unsigned P = (unsigned)sh_P;

    // ---- Phase B: re-stream full image (L2-hot), compact candidates ----
    #pragma unroll
    for (int a = 0; a < 3; ++a) {
        const float* p13 = b13 + (size_t)a * 85 * CS13;
        const float* p26 = b26 + (size_t)a * 85 * CS26;
        const float* p52 = b52 + (size_t)a * 85 * CS52;
        if (tid < CS13) {
            float v = p13[tid];
            if (v > lthr && (fkey_(v) >> 20) >= P) {
                int n = BASE13 + tid * 3 + a;
                int pos = atomicAdd(&sh_cnt, 1);
                if (pos < LCAP)
                    ckey[pos] = ((unsigned long long)__float_as_uint(sigmoidf_(v)) << 32)
                                | (unsigned)(~(unsigned)n);
            }
        }
        if (tid < CS26) {
            float v = p26[tid];
            if (v > lthr && (fkey_(v) >> 20) >= P) {
                int n = BASE26 + tid * 3 + a;
                int pos = atomicAdd(&sh_cnt, 1);
                if (pos < LCAP)
                    ckey[pos] = ((unsigned long long)__float_as_uint(sigmoidf_(v)) << 32)
                                | (unsigned)(~(unsigned)n);
            }
        }
        if (tid < N52V) {
            float4 q = ((const float4*)p52)[tid];
            float vv[4] = {q.x, q.y, q.z, q.w};
            #pragma unroll
            for (int j = 0; j < 4; ++j) {
                float v = vv[j];
                if (v > lthr && (fkey_(v) >> 20) >= P) {
                    int n = BASE52 + (tid * 4 + j) * 3 + a;
                    int pos = atomicAdd(&sh_cnt, 1);
                    if (pos < LCAP)
                        ckey[pos] = ((unsigned long long)__float_as_uint(sigmoidf_(v)) << 32)
                                    | (unsigned)(~(unsigned)n);
                }
            }
        }
    }
    __syncthreads();
    int cnt = sh_cnt; if (cnt > LCAP) cnt = LCAP;
    const int nslice = (cnt + 63) >> 6;

    // ---- exact stable rank on conf keys ----
    {
        int slice = tid >> 8;
        int e = tid & 255;
        if (slice < nslice) {
            unsigned long long mykey = ckey[e];
            if (mykey != 0ull) {
                int c2 = 0;
                int j0 = slice * 64;
                #pragma unroll 16
                for (int j = 0; j < 64; ++j)
                    if (ckey[j0 + j] > mykey) c2++;
                if (c2) atomicAdd(&srank[e], (unsigned)c2);
            }
        }
    }
    __syncthreads();
    if (tid < LCAP) {
        unsigned long long k = ckey[tid];
        if (k != 0ull) {
            unsigned r = srank[tid];
            if (r < KNMS) selkey[r] = k;
        }
    }
    __syncthreads();
    if (tid < KNMS) g_selkey[b * KNMS + tid] = selkey[tid];
}

// ============================================================
// K2: decode (13 CTAs/image, 128 thr) + fused NMS in the
// last-arriving CTA of each image.
// ============================================================
__device__ __forceinline__ void decode_emit(
    int b, int box, int lane, float v0, float v1, float v2,
    int x, int y, float strd, float aw, float ah)
{
    float ch0 = __shfl_sync(0xffffffffu, v0, 0);
    float ch1 = __shfl_sync(0xffffffffu, v0, 1);
    float ch2 = __shfl_sync(0xffffffffu, v0, 2);
    float ch3 = __shfl_sync(0xffffffffu, v0, 3);
    float ch4 = __shfl_sync(0xffffffffu, v0, 4);

    float bv = -3.402823466e+38f;
    int bi = 0x7FFFFFFF;
    if (lane >= 5)            { bv = v0; bi = lane - 5; }
    if (v1 > bv)              { bv = v1; bi = lane + 27; }
    if (lane < 21 && v2 > bv) { bv = v2; bi = lane + 59; }
    #pragma unroll
    for (int off = 16; off; off >>= 1) {
        float ov = __shfl_xor_sync(0xffffffffu, bv, off);
        int oi = __shfl_xor_sync(0xffffffffu, bi, off);
        if (ov > bv || (ov == bv && oi < bi)) { bv = ov; bi = oi; }
    }

    if (lane == 0) {
        float conf = sigmoidf_(ch0);
        float sx = sigmoidf_(ch1);
        float sy = sigmoidf_(ch2);
        float ww = expf(ch3) * aw;
        float hh = expf(ch4) * ah;
        float ox = ((float)x + sx) * strd;
        float oy = ((float)y + sy) * strd;
        float* d = g_dec + ((size_t)b * KNMS + box) * 6;
        d[0] = ox - 0.5f * ww;
        d[1] = oy - 0.5f * hh;
        d[2] = ox + 0.5f * ww;
        d[3] = oy + 0.5f * hh;
        d[4] = (float)bi;
        d[5] = conf;
    }
}

__global__ void __launch_bounds__(128)
decode_nms_kernel(const float* __restrict__ o13, const float* __restrict__ o26,
                  const float* __restrict__ o52, const float* __restrict__ anc,
                  float* __restrict__ out, int B)
{
    int blk = blockIdx.x;
    int b = blk / DBLK, chunk = blk - b * DBLK;
    int wid = threadIdx.x >> 5, lane = threadIdx.x & 31;
    int pi = chunk * 4 + wid;                 // 0..51 always (chunk<=12, wid<=3)
    int boxA = pi;
    int boxB = pi + 52;
    bool hasB = (boxB < KNMS);

    __shared__ int sh_last;
    __shared__ float sbox[KNMS * 6];
    __shared__ float sarea[KNMS];
    __shared__ unsigned sup[KNMS * 4];
    __shared__ unsigned keep0w[4], keepw[4];

    if (pi < 52) {
        unsigned idxA = ~(unsigned)(g_selkey[b * KNMS + boxA] & 0xFFFFFFFFu);
        int SA, csA, baseA; float strdA; const float* inA; const float* arowA;
        if (idxA < BASE26)      { SA = 13; csA = CS13; baseA = BASE13; strdA = 32.f; inA = o13; arowA = anc + 0; }
        else if (idxA < BASE52) { SA = 26; csA = CS26; baseA = BASE26; strdA = 16.f; inA = o26; arowA = anc + 6; }
        else                    { SA = 52; csA = CS52; baseA = BASE52; strdA = 8.f;  inA = o52; arowA = anc + 12; }
        int mA = (int)idxA - baseA;
        int cellA = mA / 3, aA = mA - cellA * 3;
        int yA = cellA / SA, xA = cellA - yA * SA;
        const float* pA = inA + ((size_t)b * 255 + (size_t)aA * 85) * csA + cellA;

        unsigned idxB = hasB ? ~(unsigned)(g_selkey[b * KNMS + boxB] & 0xFFFFFFFFu) : idxA;
        int SB, csB, baseB; float strdB; const float* inB; const float* arowB;
        if (idxB < BASE26)      { SB = 13; csB = CS13; baseB = BASE13; strdB = 32.f; inB = o13; arowB = anc + 0; }
        else if (idxB < BASE52) { SB = 26; csB = CS26; baseB = BASE26; strdB = 16.f; inB = o26; arowB = anc + 6; }
        else                    { SB = 52; csB = CS52; baseB = BASE52; strdB = 8.f;  inB = o52; arowB = anc + 12; }
        int mB = (int)idxB - baseB;
        int cellB = mB / 3, aB = mB - cellB * 3;
        int yB = cellB / SB, xB = cellB - yB * SB;
        const float* pB = inB + ((size_t)b * 255 + (size_t)aB * 85) * csB + cellB;

        float a0 = pA[(size_t)lane * csA];
        float a1 = pA[(size_t)(lane + 32) * csA];
        float a2 = (lane < 21) ? pA[(size_t)(lane + 64) * csA] : 0.f;
        float b0 = pB[(size_t)lane * csB];
        float b1 = pB[(size_t)(lane + 32) * csB];
        float b2 = (lane < 21) ? pB[(size_t)(lane + 64) * csB] : 0.f;

        decode_emit(b, boxA, lane, a0, a1, a2, xA, yA, strdA,
                    arowA[aA * 2 + 0], arowA[aA * 2 + 1]);
        if (hasB)
            decode_emit(b, boxB, lane, b0, b1, b2, xB, yB, strdB,
                        arowB[aB * 2 + 0], arowB[aB * 2 + 1]);
    }

    // ---- arrival; last CTA of this image runs NMS ----
    __threadfence();
    __syncthreads();
    if (threadIdx.x == 0) {
        unsigned old = atomicAdd(&g_decctr[b], 1u);
        sh_last = ((old % (unsigned)DBLK) == (unsigned)(DBLK - 1)) ? 1 : 0;
    }
    __syncthreads();
    if (!sh_last) return;

    const int t = threadIdx.x;
    if (t < 4) keep0w[t] = 0u;
    for (int i = t; i < KNMS * 6; i += 128) sbox[i] = g_dec[(size_t)b * KNMS * 6 + i];
    __syncthreads();
    if (t < KNMS) {
        sarea[t] = fmaxf(sbox[t * 6 + 2] - sbox[t * 6 + 0], 0.f) *
                   fmaxf(sbox[t * 6 + 3] - sbox[t * 6 + 1], 0.f);
        if ((unsigned)(g_selkey[b * KNMS + t] >> 32) != 0u)
            atomicOr(&keep0w[t >> 5], 1u << (t & 31));
    }
    __syncthreads();

    for (int w = t; w < KNMS * 4; w += 128) {
        int i = w >> 2, c = w & 3;
        unsigned m = 0;
        float ix1 = sbox[i * 6 + 0], iy1 = sbox[i * 6 + 1];
        float ix2 = sbox[i * 6 + 2], iy2 = sbox[i * 6 + 3];
        float icls = sbox[i * 6 + 4], iar = sarea[i];
        int j0 = c * 32;
        #pragma unroll 8
        for (int jj = 0; jj < 32; ++jj) {
            int j = j0 + jj;
            if (j > i && j < KNMS && sbox[j * 6 + 4] == icls) {
                float x1 = fmaxf(ix1, sbox[j * 6 + 0]);
                float y1 = fmaxf(iy1, sbox[j * 6 + 1]);
                float x2 = fminf(ix2, sbox[j * 6 + 2]);
                float y2 = fminf(iy2, sbox[j * 6 + 3]);
                float inter = fmaxf(x2 - x1, 0.f) * fmaxf(y2 - y1, 0.f);
                float uni = iar + sarea[j] - inter;
                if (inter / fmaxf(uni, 1e-9f) > IOU_THR) m |= (1u << jj);
            }
        }
        sup[w] = m;
    }
    __syncthreads();

    if (t == 0) {
        unsigned k0 = keep0w[0], k1 = keep0w[1], k2 = keep0w[2], k3 = keep0w[3];
        unsigned n0 = sup[0], n1 = sup[1], n2 = sup[2], n3 = sup[3];
        for (int i = 0; i < KNMS; ++i) {
            unsigned s0 = n0, s1 = n1, s2 = n2, s3 = n3;
            if (i + 1 < KNMS) {
                n0 = sup[(i + 1) * 4 + 0];
                n1 = sup[(i + 1) * 4 + 1];
                n2 = sup[(i + 1) * 4 + 2];
                n3 = sup[(i + 1) * 4 + 3];
            }
            unsigned word = (i < 32) ? k0 : (i < 64) ? k1 : (i < 96) ? k2 : k3;
            unsigned msk = (unsigned)(-(int)((word >> (i & 31)) & 1u));
            k0 &= ~(s0 & msk);
            k1 &= ~(s1 & msk);
            k2 &= ~(s2 & msk);
            k3 &= ~(s3 & msk);
        }
        keepw[0] = k0; keepw[1] = k1; keepw[2] = k2; keepw[3] = k3;
    }
    __syncthreads();

    float* out_sel = out;
    float* out_keep = out + (size_t)B * KNMS * 6;
    if (t < KNMS) {
        #pragma unroll
        for (int c = 0; c < 6; ++c)
            out_sel[((size_t)b * KNMS + t) * 6 + c] = sbox[t * 6 + c];
        out_keep[(size_t)b * KNMS + t] =
            ((keepw[t >> 5] >> (t & 31)) & 1u) ? 1.0f : 0.0f;
    }
}

// ============================================================
extern "C" void kernel_launch(void* const* d_in, const int* in_sizes, int n_in,
                              void* d_out, int out_size)
{
    const float* o13 = (const float*)d_in[0];
    const float* o26 = (const float*)d_in[1];
    const float* o52 = (const float*)d_in[2];
    const float* anc = (const float*)d_in[3];   // [3,3,2]
    const float* thr = (const float*)d_in[4];   // scalar

    int B = in_sizes[0] / (255 * CS13);
    if (B > BMAX) B = BMAX;
    float* out = (float*)d_out;

    select_kernel<<<B * 4, 1024>>>(o13, o26, o52, thr, B);
    decode_nms_kernel<<<B * DBLK, 128>>>(o13, o26, o52, anc, out, B);
}

// round 14
// speedup vs baseline: 1.3751x; 1.3751x over previous
#include <cuda_runtime.h>
#include <cstdint>

// ---------------- problem constants ----------------
#define KNMS 100
#define BMAX 32
#define IOU_THR 0.3f

#define CS13 169
#define CS26 676
#define CS52 2704
#define N52V 676            // CS52/4 float4 per 52-scale anchor plane
#define BASE13 0
#define BASE26 507
#define BASE52 2535
#define LCAP 256
#define DBLK 13             // decode blocks per image
#define NBIN 4096           // 12-bit monotone-key histogram

// ---------------- device scratch ----------------
__device__ unsigned g_hist4[(size_t)BMAX * 4 * NBIN];   // per-CTA histogram slices
__device__ unsigned g_selctr[BMAX];                     // monotone arrival counters
__device__ unsigned long long g_selkey[BMAX * KNMS];    // sorted top-100 keys
__device__ float g_dec[BMAX * KNMS * 6];                // decoded boxes, rank order

__device__ __forceinline__ float sigmoidf_(float x) {
    return 1.0f / (1.0f + expf(-x));
}
__device__ __forceinline__ unsigned fkey_(float x) {    // monotone float->uint
    unsigned b = __float_as_uint(x);
    return (b & 0x80000000u) ? ~b : (b | 0x80000000u);
}

// ============================================================
// K1: top-100 select, 4 CTAs per image (grid = B*4, 1024 thr).
// Each CTA histograms 1/4 of the conf values (shared) and dumps
// its slice to global. Last-arriving CTA sums slices, picks the
// threshold bin, compacts candidates from the (L2-hot) inputs,
// and computes the exact stable rank -> g_selkey.
// ============================================================
__global__ void __launch_bounds__(1024)
select_kernel(const float* __restrict__ o13, const float* __restrict__ o26,
              const float* __restrict__ o52, const float* __restrict__ thr_p, int B)
{
    const int blk = blockIdx.x;
    const int b = blk >> 2;
    const int c = blk & 3;
    const int tid = threadIdx.x;
    const int lane = tid & 31;

    __shared__ unsigned hist[NBIN];               // 16 KB
    __shared__ unsigned psum[1024];
    __shared__ unsigned csum[128];
    __shared__ unsigned long long ckey[LCAP];
    __shared__ unsigned srank[LCAP];
    __shared__ unsigned long long selkey[KNMS];
    __shared__ int sh_cb, sh_kres, sh_P, sh_cnt, sh_islast;

    const float thr = *thr_p;
    const float lthr = logf(thr / (1.0f - thr)); // conf > thr  <=>  logit > lthr

    const float* b13 = o13 + (size_t)b * 255 * CS13;
    const float* b26 = o26 + (size_t)b * 255 * CS26;
    const float* b52 = o52 + (size_t)b * 255 * CS52;

    ((uint4*)hist)[tid] = make_uint4(0u, 0u, 0u, 0u);
    if (tid == 0) sh_cnt = 0;
    __syncthreads();

    // ---- Phase A (quarter): 52-scale vec quarter + one small scale ----
    if (tid < 3 * 169) {                          // 3 anchors x 169 float4
        int a = tid / 169, vv = tid - a * 169;
        int v = c * 169 + vv;
        float4 q = ((const float4*)(b52 + (size_t)a * 85 * CS52))[v];
        if (q.x > lthr) atomicAdd(&hist[fkey_(q.x) >> 20], 1u);
        if (q.y > lthr) atomicAdd(&hist[fkey_(q.y) >> 20], 1u);
        if (q.z > lthr) atomicAdd(&hist[fkey_(q.z) >> 20], 1u);
        if (q.w > lthr) atomicAdd(&hist[fkey_(q.w) >> 20], 1u);
    }
    if (c == 0) {
        if (tid < 3 * CS13) {                     // whole 13-scale
            int a = tid / CS13, cell = tid - a * CS13;
            float v = b13[(size_t)a * 85 * CS13 + cell];
            if (v > lthr) atomicAdd(&hist[fkey_(v) >> 20], 1u);
        }
    } else {
        if (tid < CS26) {                         // anchor (c-1) of 26-scale
            float v = b26[(size_t)(c - 1) * 85 * CS26 + tid];
            if (v > lthr) atomicAdd(&hist[fkey_(v) >> 20], 1u);
        }
    }
    __syncthreads();

    // ---- dump slice, signal arrival ----
    ((uint4*)(g_hist4 + (size_t)blk * NBIN))[tid] = ((uint4*)hist)[tid];
    __threadfence();
    __syncthreads();
    if (tid == 0) {
        unsigned old = atomicAdd(&g_selctr[b], 1u);
        sh_islast = ((old & 3u) == 3u) ? 1 : 0;   // monotone counter: replay-safe
    }
    __syncthreads();
    if (!sh_islast) return;

    // ---- last CTA: sum the 4 slices ----
    {
        const uint4* h0 = (const uint4*)(g_hist4 + (size_t)(b * 4 + 0) * NBIN);
        const uint4* h1 = (const uint4*)(g_hist4 + (size_t)(b * 4 + 1) * NBIN);
        const uint4* h2 = (const uint4*)(g_hist4 + (size_t)(b * 4 + 2) * NBIN);
        const uint4* h3 = (const uint4*)(g_hist4 + (size_t)(b * 4 + 3) * NBIN);
        uint4 q0 = h0[tid], q1 = h1[tid], q2 = h2[tid], q3 = h3[tid];
        uint4 s;
        s.x = q0.x + q1.x + q2.x + q3.x;
        s.y = q0.y + q1.y + q2.y + q3.y;
        s.z = q0.z + q1.z + q2.z + q3.z;
        s.w = q0.w + q1.w + q2.w + q3.w;
        ((uint4*)hist)[tid] = s;
        psum[tid] = s.x + s.y + s.z + s.w;
    }
    __syncthreads();
    if (tid < 128) {
        uint4 a0 = ((uint4*)psum)[tid * 2];
        uint4 a1 = ((uint4*)psum)[tid * 2 + 1];
        csum[tid] = a0.x + a0.y + a0.z + a0.w + a1.x + a1.y + a1.z + a1.w;
    }
    __syncthreads();

    // ---- warp 0: coarse + fine threshold pick ----
    if (tid < 32) {
        unsigned cc[4];
        int T = 0;
        #pragma unroll
        for (int r = 0; r < 4; ++r) { cc[r] = csum[lane * 4 + r]; T += (int)cc[r]; }
        int S = T;
        #pragma unroll
        for (int off = 1; off < 32; off <<= 1) {
            int v = __shfl_down_sync(0xffffffffu, S, off);
            if (lane + off < 32) S += v;
        }
        int Snext = __shfl_down_sync(0xffffffffu, S, 1);
        if (lane == 31) Snext = 0;
        if (S >= KNMS && Snext < KNMS) {
            int rem = Snext;
            #pragma unroll
            for (int r = 3; r >= 0; --r) {
                if (rem + (int)cc[r] >= KNMS) {
                    sh_cb = lane * 4 + r;
                    sh_kres = KNMS - rem;
                    break;
                }
                rem += (int)cc[r];
            }
        }
        __syncwarp();
        int cb = sh_cb, kres = sh_kres;
        unsigned h = hist[cb * 32 + lane];
        int S2 = (int)h;
        #pragma unroll
        for (int off = 1; off < 32; off <<= 1) {
            int v = __shfl_down_sync(0xffffffffu, S2, off);
            if (lane + off < 32) S2 += v;
        }
        int S2n = __shfl_down_sync(0xffffffffu, S2, 1);
        if (lane == 31) S2n = 0;
        if (S2 >= kres && S2n < kres) sh_P = cb * 32 + lane;
    }
    if (tid < LCAP) { ckey[tid] = 0ull; srank[tid] = 0u; }
    if (tid < KNMS) selkey[tid] = 0ull;
    __syncthreads();
    const unsigned P = (unsigned)sh_P;

    // ---- Phase B: re-stream full image (L2-hot), compact candidates ----
    #pragma unroll
    for (int a = 0; a < 3; ++a) {
        const float* p13 = b13 + (size_t)a * 85 * CS13;
        const float* p26 = b26 + (size_t)a * 85 * CS26;
        const float* p52 = b52 + (size_t)a * 85 * CS52;
        if (tid < CS13) {
            float v = p13[tid];
            if (v > lthr && (fkey_(v) >> 20) >= P) {
                int n = BASE13 + tid * 3 + a;
                int pos = atomicAdd(&sh_cnt, 1);
                if (pos < LCAP)
                    ckey[pos] = ((unsigned long long)__float_as_uint(sigmoidf_(v)) << 32)
                                | (unsigned)(~(unsigned)n);
            }
        }
        if (tid < CS26) {
            float v = p26[tid];
            if (v > lthr && (fkey_(v) >> 20) >= P) {
                int n = BASE26 + tid * 3 + a;
                int pos = atomicAdd(&sh_cnt, 1);
                if (pos < LCAP)
                    ckey[pos] = ((unsigned long long)__float_as_uint(sigmoidf_(v)) << 32)
                                | (unsigned)(~(unsigned)n);
            }
        }
        if (tid < N52V) {
            float4 q = ((const float4*)p52)[tid];
            float vv[4] = {q.x, q.y, q.z, q.w};
            #pragma unroll
            for (int j = 0; j < 4; ++j) {
                float v = vv[j];
                if (v > lthr && (fkey_(v) >> 20) >= P) {
                    int n = BASE52 + (tid * 4 + j) * 3 + a;
                    int pos = atomicAdd(&sh_cnt, 1);
                    if (pos < LCAP)
                        ckey[pos] = ((unsigned long long)__float_as_uint(sigmoidf_(v)) << 32)
                                    | (unsigned)(~(unsigned)n);
                }
            }
        }
    }
    __syncthreads();
    int cnt = sh_cnt; if (cnt > LCAP) cnt = LCAP;
    const int nslice = (cnt + 63) >> 6;

    // ---- exact stable rank on conf keys ----
    {
        int slice = tid >> 8;
        int e = tid & 255;
        if (slice < nslice) {
            unsigned long long mykey = ckey[e];
            if (mykey != 0ull) {
                int c2 = 0;
                int j0 = slice * 64;
                #pragma unroll 16
                for (int j = 0; j < 64; ++j)
                    if (ckey[j0 + j] > mykey) c2++;
                if (c2) atomicAdd(&srank[e], (unsigned)c2);
            }
        }
    }
    __syncthreads();
    if (tid < LCAP) {
        unsigned long long k = ckey[tid];
        if (k != 0ull) {
            unsigned r = srank[tid];
            if (r < KNMS) selkey[r] = k;
        }
    }
    __syncthreads();
    if (tid < KNMS) g_selkey[b * KNMS + tid] = selkey[tid];
}

// ============================================================
// K2: decode gather — 416 CTAs for chip-wide MLP. 128 thr/block,
// one warp handles 2 boxes; all scattered loads issued up front.
// (Lean: no fence, no counter, no NMS baggage — measured-good.)
// ============================================================
__device__ __forceinline__ void decode_emit(
    int b, int box, int lane, float v0, float v1, float v2,
    int x, int y, float strd, float aw, float ah)
{
    float ch0 = __shfl_sync(0xffffffffu, v0, 0);
    float ch1 = __shfl_sync(0xffffffffu, v0, 1);
    float ch2 = __shfl_sync(0xffffffffu, v0, 2);
    float ch3 = __shfl_sync(0xffffffffu, v0, 3);
    float ch4 = __shfl_sync(0xffffffffu, v0, 4);

    float bv = -3.402823466e+38f;
    int bi = 0x7FFFFFFF;
    if (lane >= 5)            { bv = v0; bi = lane - 5; }
    if (v1 > bv)              { bv = v1; bi = lane + 27; }
    if (lane < 21 && v2 > bv) { bv = v2; bi = lane + 59; }
    #pragma unroll
    for (int off = 16; off; off >>= 1) {
        float ov = __shfl_xor_sync(0xffffffffu, bv, off);
        int oi = __shfl_xor_sync(0xffffffffu, bi, off);
        if (ov > bv || (ov == bv && oi < bi)) { bv = ov; bi = oi; }
    }

    if (lane == 0) {
        float conf = sigmoidf_(ch0);
        float sx = sigmoidf_(ch1);
        float sy = sigmoidf_(ch2);
        float ww = expf(ch3) * aw;
        float hh = expf(ch4) * ah;
        float ox = ((float)x + sx) * strd;
        float oy = ((float)y + sy) * strd;
        float* d = g_dec + ((size_t)b * KNMS + box) * 6;
        d[0] = ox - 0.5f * ww;
        d[1] = oy - 0.5f * hh;
        d[2] = ox + 0.5f * ww;
        d[3] = oy + 0.5f * hh;
        d[4] = (float)bi;
        d[5] = conf;
    }
}

__global__ void __launch_bounds__(128)
decode_kernel(const float* __restrict__ o13, const float* __restrict__ o26,
              const float* __restrict__ o52, const float* __restrict__ anc, int B)
{
    int blk = blockIdx.x;
    int b = blk / DBLK, chunk = blk - b * DBLK;
    int wid = threadIdx.x >> 5, lane = threadIdx.x & 31;
    int pi = chunk * 4 + wid;                 // 0..51
    if (pi >= 52) return;
    int boxA = pi;
    int boxB = pi + 52;
    bool hasB = (boxB < KNMS);

    unsigned idxA = ~(unsigned)(g_selkey[b * KNMS + boxA] & 0xFFFFFFFFu);
    int SA, csA, baseA; float strdA; const float* inA; const float* arowA;
    if (idxA < BASE26)      { SA = 13; csA = CS13; baseA = BASE13; strdA = 32.f; inA = o13; arowA = anc + 0; }
    else if (idxA < BASE52) { SA = 26; csA = CS26; baseA = BASE26; strdA = 16.f; inA = o26; arowA = anc + 6; }
    else                    { SA = 52; csA = CS52; baseA = BASE52; strdA = 8.f;  inA = o52; arowA = anc + 12; }
    int mA = (int)idxA - baseA;
    int cellA = mA / 3, aA = mA - cellA * 3;
    int yA = cellA / SA, xA = cellA - yA * SA;
    const float* pA = inA + ((size_t)b * 255 + (size_t)aA * 85) * csA + cellA;

    unsigned idxB = hasB ? ~(unsigned)(g_selkey[b * KNMS + boxB] & 0xFFFFFFFFu) : idxA;
    int SB, csB, baseB; float strdB; const float* inB; const float* arowB;
    if (idxB < BASE26)      { SB = 13; csB = CS13; baseB = BASE13; strdB = 32.f; inB = o13; arowB = anc + 0; }
    else if (idxB < BASE52) { SB = 26; csB = CS26; baseB = BASE26; strdB = 16.f; inB = o26; arowB = anc + 6; }
    else                    { SB = 52; csB = CS52; baseB = BASE52; strdB = 8.f;  inB = o52; arowB = anc + 12; }
    int mB = (int)idxB - baseB;
    int cellB = mB / 3, aB = mB - cellB * 3;
    int yB = cellB / SB, xB = cellB - yB * SB;
    const float* pB = inB + ((size_t)b * 255 + (size_t)aB * 85) * csB + cellB;

    float a0 = pA[(size_t)lane * csA];
    float a1 = pA[(size_t)(lane + 32) * csA];
    float a2 = (lane < 21) ? pA[(size_t)(lane + 64) * csA] : 0.f;
    float b0 = pB[(size_t)lane * csB];
    float b1 = pB[(size_t)(lane + 32) * csB];
    float b2 = (lane < 21) ? pB[(size_t)(lane + 64) * csB] : 0.f;

    decode_emit(b, boxA, lane, a0, a1, a2, xA, yA, strdA,
                arowA[aA * 2 + 0], arowA[aA * 2 + 1]);
    if (hasB)
        decode_emit(b, boxB, lane, b0, b1, b2, xB, yB, strdB,
                    arowB[aB * 2 + 0], arowB[aB * 2 + 1]);
}

// ============================================================
// K3: NMS — one block/image, 512 thr (sup build in one pass).
// ============================================================
__global__ void __launch_bounds__(512)
nms_kernel(float* __restrict__ out, int B)
{
    const int b = blockIdx.x;
    const int t = threadIdx.x;

    __shared__ float sbox[KNMS * 6];
    __shared__ float sarea[KNMS];
    __shared__ unsigned sup[KNMS * 4];
    __shared__ unsigned keep0w[4], keepw[4];

    if (t < 4) keep0w[t] = 0u;
    for (int i = t; i < KNMS * 6; i += 512) sbox[i] = g_dec[(size_t)b * KNMS * 6 + i];
    __syncthreads();
    if (t < KNMS) {
        sarea[t] = fmaxf(sbox[t * 6 + 2] - sbox[t * 6 + 0], 0.f) *
                   fmaxf(sbox[t * 6 + 3] - sbox[t * 6 + 1], 0.f);
        if ((unsigned)(g_selkey[b * KNMS + t] >> 32) != 0u)
            atomicOr(&keep0w[t >> 5], 1u << (t & 31));
    }
    __syncthreads();

    if (t < KNMS * 4) {
        int i = t >> 2, c = t & 3;
        unsigned m = 0;
        float ix1 = sbox[i * 6 + 0], iy1 = sbox[i * 6 + 1];
        float ix2 = sbox[i * 6 + 2], iy2 = sbox[i * 6 + 3];
        float icls = sbox[i * 6 + 4], iar = sarea[i];
        int j0 = c * 32;
        #pragma unroll 8
        for (int jj = 0; jj < 32; ++jj) {
            int j = j0 + jj;
            if (j > i && j < KNMS && sbox[j * 6 + 4] == icls) {
                float x1 = fmaxf(ix1, sbox[j * 6 + 0]);
                float y1 = fmaxf(iy1, sbox[j * 6 + 1]);
                float x2 = fminf(ix2, sbox[j * 6 + 2]);
                float y2 = fminf(iy2, sbox[j * 6 + 3]);
                float inter = fmaxf(x2 - x1, 0.f) * fmaxf(y2 - y1, 0.f);
                float uni = iar + sarea[j] - inter;
                if (inter / fmaxf(uni, 1e-9f) > IOU_THR) m |= (1u << jj);
            }
        }
        sup[t] = m;
    }
    __syncthreads();

    if (t == 0) {
        unsigned k0 = keep0w[0], k1 = keep0w[1], k2 = keep0w[2], k3 = keep0w[3];
        unsigned n0 = sup[0], n1 = sup[1], n2 = sup[2], n3 = sup[3];
        for (int i = 0; i < KNMS; ++i) {
            unsigned s0 = n0, s1 = n1, s2 = n2, s3 = n3;
            if (i + 1 < KNMS) {
                n0 = sup[(i + 1) * 4 + 0];
                n1 = sup[(i + 1) * 4 + 1];
                n2 = sup[(i + 1) * 4 + 2];
                n3 = sup[(i + 1) * 4 + 3];
            }
            unsigned word = (i < 32) ? k0 : (i < 64) ? k1 : (i < 96) ? k2 : k3;
            unsigned msk = (unsigned)(-(int)((word >> (i & 31)) & 1u));
            k0 &= ~(s0 & msk);
            k1 &= ~(s1 & msk);
            k2 &= ~(s2 & msk);
            k3 &= ~(s3 & msk);
        }
        keepw[0] = k0; keepw[1] = k1; keepw[2] = k2; keepw[3] = k3;
    }
    __syncthreads();

    float* out_sel = out;
    float* out_keep = out + (size_t)B * KNMS * 6;
    if (t < KNMS) {
        #pragma unroll
        for (int c = 0; c < 6; ++c)
            out_sel[((size_t)b * KNMS + t) * 6 + c] = sbox[t * 6 + c];
        out_keep[(size_t)b * KNMS + t] =
            ((keepw[t >> 5] >> (t & 31)) & 1u) ? 1.0f : 0.0f;
    }
}

// ============================================================
extern "C" void kernel_launch(void* const* d_in, const int* in_sizes, int n_in,
                              void* d_out, int out_size)
{
    const float* o13 = (const float*)d_in[0];
    const float* o26 = (const float*)d_in[1];
    const float* o52 = (const float*)d_in[2];
    const float* anc = (const float*)d_in[3];   // [3,3,2]
    const float* thr = (const float*)d_in[4];   // scalar

    int B = in_sizes[0] / (255 * CS13);
    if (B > BMAX) B = BMAX;
    float* out = (float*)d_out;

    select_kernel<<<B * 4, 1024>>>(o13, o26, o52, thr, B);
    decode_kernel<<<B * DBLK, 128>>>(o13, o26, o52, anc, B);
    nms_kernel<<<B, 512>>>(out, B);
}